// round 1
// baseline (speedup 1.0000x reference)
#include <cuda_runtime.h>
#include <cuda_bf16.h>
#include <math.h>

#define BB 8
#define NN 1024
#define FIN 256
#define FOUT 256
#define HH 4
#define DD 64
#define ROWS 32

// scratch (no cudaMalloc allowed)
__device__ float g_h[BB * NN * FOUT];     // normalized h
__device__ float g_ei[BB * NN * HH];      // a_src . h  per (b,n,h)
__device__ float g_ej[BB * NN * HH];      // a_dst . h  per (b,n,h)

// ---------------------------------------------------------------------------
// Kernel 1: h = LN(x @ W) * gamma + beta ; e_i = h.a_src ; e_j = h.a_dst
// One block = 32 rows x 256 outputs. 256 threads, reg-blocked 8x4.
// ---------------------------------------------------------------------------
__global__ void __launch_bounds__(256, 2) gemm_ln_kernel(
    const float* __restrict__ x, const float* __restrict__ W,
    const float* __restrict__ gamma, const float* __restrict__ beta,
    const float* __restrict__ a)
{
    __shared__ float xs[ROWS * FIN];   // 32KB; reused as h-staging after GEMM
    const int tid = threadIdx.x;
    const size_t row_base = (size_t)blockIdx.x * ROWS;

    // load 32 rows of x (coalesced float4)
    {
        const float4* x4 = (const float4*)(x + row_base * FIN);
        float4* xs4 = (float4*)xs;
        #pragma unroll
        for (int idx = tid; idx < ROWS * FIN / 4; idx += 256)
            xs4[idx] = x4[idx];
    }
    __syncthreads();

    const int cid = tid & 63;          // 64 col-groups of 4 cols
    const int rid = tid >> 6;          // 4 row-groups of 8 rows
    const int r0 = rid * 8;

    float acc[8][4];
    #pragma unroll
    for (int r = 0; r < 8; r++)
        #pragma unroll
        for (int j = 0; j < 4; j++) acc[r][j] = 0.0f;

    const float4* W4 = (const float4*)W;
    #pragma unroll 4
    for (int f = 0; f < FIN; f++) {
        float4 w = W4[f * 64 + cid];           // coalesced, L1-resident
        const float* xrow = xs + r0 * FIN + f;
        #pragma unroll
        for (int r = 0; r < 8; r++) {
            float xv = xrow[r * FIN];          // warp-broadcast LDS
            acc[r][0] = fmaf(xv, w.x, acc[r][0]);
            acc[r][1] = fmaf(xv, w.y, acc[r][1]);
            acc[r][2] = fmaf(xv, w.z, acc[r][2]);
            acc[r][3] = fmaf(xv, w.w, acc[r][3]);
        }
    }
    __syncthreads();

    // stage h into smem (reuse xs)
    {
        float4* hs4 = (float4*)xs;
        #pragma unroll
        for (int r = 0; r < 8; r++)
            hs4[(r0 + r) * 64 + cid] = make_float4(acc[r][0], acc[r][1], acc[r][2], acc[r][3]);
    }
    __syncthreads();

    // LayerNorm + logits: one warp per row
    const int wid = tid >> 5, lane = tid & 31;
    for (int rr = wid; rr < ROWS; rr += 8) {
        float v[8];
        float s = 0.0f, ss = 0.0f;
        #pragma unroll
        for (int k = 0; k < 8; k++) {
            v[k] = xs[rr * FIN + lane + 32 * k];
            s += v[k];
            ss = fmaf(v[k], v[k], ss);
        }
        #pragma unroll
        for (int o = 16; o; o >>= 1) {
            s  += __shfl_xor_sync(0xffffffffu, s,  o);
            ss += __shfl_xor_sync(0xffffffffu, ss, o);
        }
        const float mu = s * (1.0f / FOUT);
        const float var = ss * (1.0f / FOUT) - mu * mu;
        const float rstd = rsqrtf(var + 1e-5f);

        const size_t row = row_base + rr;
        float es[4] = {0, 0, 0, 0}, ed[4] = {0, 0, 0, 0};
        #pragma unroll
        for (int k = 0; k < 8; k++) {
            const int col = lane + 32 * k;
            const float n = fmaf((v[k] - mu) * rstd, gamma[col], beta[col]);
            g_h[row * FOUT + col] = n;
            const int hh = k >> 1;
            const int d = lane + 32 * (k & 1);
            es[hh] = fmaf(n, a[d], es[hh]);
            ed[hh] = fmaf(n, a[DD + d], ed[hh]);
        }
        #pragma unroll
        for (int o = 16; o; o >>= 1) {
            #pragma unroll
            for (int hh = 0; hh < 4; hh++) {
                es[hh] += __shfl_xor_sync(0xffffffffu, es[hh], o);
                ed[hh] += __shfl_xor_sync(0xffffffffu, ed[hh], o);
            }
        }
        if (lane == 0) {
            #pragma unroll
            for (int hh = 0; hh < 4; hh++) {
                g_ei[row * HH + hh] = es[hh];
                g_ej[row * HH + hh] = ed[hh];
            }
        }
    }
}

// ---------------------------------------------------------------------------
// Kernel 2: per (b,i): neighbor compaction -> leakyrelu scores -> softmax ->
// out[i,:] = sum_j alpha[j,h] * h[j,:].  Masked entries contribute exactly 0
// (exp(-1e9 - max) underflows to 0 in fp32), so skipping them is exact.
// Deterministic: prefix-scan compaction + fixed reduction trees, no atomics.
// ---------------------------------------------------------------------------
__global__ void __launch_bounds__(256) attn_kernel(
    const float* __restrict__ adj, float* __restrict__ out)
{
    __shared__ int   nbr[NN];          // 4KB
    __shared__ float sc[NN * HH];      // 16KB  (scores, then exp())
    __shared__ int   wsum[8];
    __shared__ int   woff[8];
    __shared__ int   Ktot_s;
    __shared__ float red[8 * HH];
    __shared__ float mxs[HH];
    __shared__ float sms[HH];

    const int tid = threadIdx.x;
    const int lane = tid & 31, wid = tid >> 5;
    const size_t bi = blockIdx.x;              // b*N + i
    const size_t b  = bi >> 10;                // N = 1024

    // ---- ordered neighbor compaction (each thread owns 4 consecutive j) ----
    const float4 av = ((const float4*)(adj + bi * NN))[tid];
    const int m0 = (av.x != 0.0f), m1 = (av.y != 0.0f), m2 = (av.z != 0.0f), m3 = (av.w != 0.0f);
    int cnt = m0 + m1 + m2 + m3;
    int pre = cnt;
    #pragma unroll
    for (int o = 1; o < 32; o <<= 1) {
        int t = __shfl_up_sync(0xffffffffu, pre, o);
        if (lane >= o) pre += t;
    }
    if (lane == 31) wsum[wid] = pre;
    __syncthreads();
    if (tid == 0) {
        int acc = 0;
        #pragma unroll
        for (int w = 0; w < 8; w++) { woff[w] = acc; acc += wsum[w]; }
        Ktot_s = acc;
    }
    __syncthreads();
    {
        int p = woff[wid] + pre - cnt;
        const int j0 = tid * 4;
        if (m0) nbr[p++] = j0;
        if (m1) nbr[p++] = j0 + 1;
        if (m2) nbr[p++] = j0 + 2;
        if (m3) nbr[p++] = j0 + 3;
    }
    __syncthreads();
    const int K = Ktot_s;

    // ---- scores: leakyrelu(e_i[b,i,h] + e_j[b,j,h]) ----
    float ei[4];
    {
        const float4 e4 = ((const float4*)g_ei)[bi];
        ei[0] = e4.x; ei[1] = e4.y; ei[2] = e4.z; ei[3] = e4.w;
    }
    float lmax[4] = {-1e30f, -1e30f, -1e30f, -1e30f};
    const float4* ej4 = (const float4*)g_ej + b * NN;
    float4* sc4 = (float4*)sc;
    for (int nn = tid; nn < K; nn += 256) {
        const int j = nbr[nn];
        const float4 e4 = ej4[j];
        float s0 = ei[0] + e4.x, s1 = ei[1] + e4.y, s2 = ei[2] + e4.z, s3 = ei[3] + e4.w;
        s0 = s0 > 0.0f ? s0 : 0.2f * s0;
        s1 = s1 > 0.0f ? s1 : 0.2f * s1;
        s2 = s2 > 0.0f ? s2 : 0.2f * s2;
        s3 = s3 > 0.0f ? s3 : 0.2f * s3;
        sc4[nn] = make_float4(s0, s1, s2, s3);
        lmax[0] = fmaxf(lmax[0], s0); lmax[1] = fmaxf(lmax[1], s1);
        lmax[2] = fmaxf(lmax[2], s2); lmax[3] = fmaxf(lmax[3], s3);
    }
    // block max per head
    #pragma unroll
    for (int o = 16; o; o >>= 1)
        #pragma unroll
        for (int h = 0; h < 4; h++)
            lmax[h] = fmaxf(lmax[h], __shfl_xor_sync(0xffffffffu, lmax[h], o));
    if (lane == 0)
        #pragma unroll
        for (int h = 0; h < 4; h++) red[wid * 4 + h] = lmax[h];
    __syncthreads();
    if (tid < 4) {
        float m = -1e30f;
        #pragma unroll
        for (int w = 0; w < 8; w++) m = fmaxf(m, red[w * 4 + tid]);
        mxs[tid] = m;
    }
    __syncthreads();
    const float mx0 = mxs[0], mx1 = mxs[1], mx2 = mxs[2], mx3 = mxs[3];

    // ---- exp + block sum per head ----
    float lsum[4] = {0, 0, 0, 0};
    for (int nn = tid; nn < K; nn += 256) {
        float4 v = sc4[nn];
        v.x = __expf(v.x - mx0);
        v.y = __expf(v.y - mx1);
        v.z = __expf(v.z - mx2);
        v.w = __expf(v.w - mx3);
        sc4[nn] = v;
        lsum[0] += v.x; lsum[1] += v.y; lsum[2] += v.z; lsum[3] += v.w;
    }
    #pragma unroll
    for (int o = 16; o; o >>= 1)
        #pragma unroll
        for (int h = 0; h < 4; h++)
            lsum[h] += __shfl_xor_sync(0xffffffffu, lsum[h], o);
    if (lane == 0)
        #pragma unroll
        for (int h = 0; h < 4; h++) red[wid * 4 + h] = lsum[h];
    __syncthreads();
    if (tid < 4) {
        float s = 0.0f;
        #pragma unroll
        for (int w = 0; w < 8; w++) s += red[w * 4 + tid];
        sms[tid] = s;
    }
    __syncthreads();

    // ---- gather-accumulate: thread owns one output column ----
    const int col = tid;
    const int hh = col >> 6;
    const float inv = 1.0f / sms[hh];
    const float* hb = g_h + b * NN * FOUT;

    float a0 = 0.0f, a1 = 0.0f, a2 = 0.0f, a3 = 0.0f;
    int nn = 0;
    for (; nn + 4 <= K; nn += 4) {
        const int j0 = nbr[nn], j1 = nbr[nn + 1], j2 = nbr[nn + 2], j3 = nbr[nn + 3];
        const float w0 = sc[(nn + 0) * 4 + hh];
        const float w1 = sc[(nn + 1) * 4 + hh];
        const float w2 = sc[(nn + 2) * 4 + hh];
        const float w3 = sc[(nn + 3) * 4 + hh];
        a0 = fmaf(w0, hb[(size_t)j0 * FOUT + col], a0);
        a1 = fmaf(w1, hb[(size_t)j1 * FOUT + col], a1);
        a2 = fmaf(w2, hb[(size_t)j2 * FOUT + col], a2);
        a3 = fmaf(w3, hb[(size_t)j3 * FOUT + col], a3);
    }
    for (; nn < K; nn++) {
        const int j = nbr[nn];
        a0 = fmaf(sc[nn * 4 + hh], hb[(size_t)j * FOUT + col], a0);
    }
    out[bi * FOUT + col] = ((a0 + a1) + (a2 + a3)) * inv;
}

extern "C" void kernel_launch(void* const* d_in, const int* in_sizes, int n_in,
                              void* d_out, int out_size)
{
    const float* x     = (const float*)d_in[0];
    const float* adj   = (const float*)d_in[1];
    const float* W     = (const float*)d_in[2];
    const float* gamma = (const float*)d_in[3];
    const float* beta  = (const float*)d_in[4];
    const float* a     = (const float*)d_in[5];
    float* out = (float*)d_out;

    gemm_ln_kernel<<<(BB * NN) / ROWS, 256>>>(x, W, gamma, beta, a);
    attn_kernel<<<BB * NN, 256>>>(adj, out);
}

// round 2
// speedup vs baseline: 1.1620x; 1.1620x over previous
#include <cuda_runtime.h>
#include <cuda_bf16.h>
#include <math.h>

#define BB 8
#define NN 1024
#define FIN 256
#define FOUT 256
#define HH 4
#define DD 64
#define ROWS 32

// scratch (no cudaMalloc allowed)
__device__ float g_h[BB * NN * FOUT];     // normalized h
__device__ float g_ei[BB * NN * HH];      // a_src . h  per (b,n,h)
__device__ float g_ej[BB * NN * HH];      // a_dst . h  per (b,n,h)

// ---------------------------------------------------------------------------
// Kernel 1: h = LN(x @ W) * gamma + beta ; e_i = h.a_src ; e_j = h.a_dst
// One block = 32 rows x 256 outputs. 256 threads, reg-blocked 8x4.
// ---------------------------------------------------------------------------
__global__ void __launch_bounds__(256, 2) gemm_ln_kernel(
    const float* __restrict__ x, const float* __restrict__ W,
    const float* __restrict__ gamma, const float* __restrict__ beta,
    const float* __restrict__ a)
{
    __shared__ float xs[ROWS * FIN];   // 32KB; reused as h-staging after GEMM
    const int tid = threadIdx.x;
    const size_t row_base = (size_t)blockIdx.x * ROWS;

    // load 32 rows of x (coalesced float4)
    {
        const float4* x4 = (const float4*)(x + row_base * FIN);
        float4* xs4 = (float4*)xs;
        #pragma unroll
        for (int idx = tid; idx < ROWS * FIN / 4; idx += 256)
            xs4[idx] = x4[idx];
    }
    __syncthreads();

    const int cid = tid & 63;          // 64 col-groups of 4 cols
    const int rid = tid >> 6;          // 4 row-groups of 8 rows
    const int r0 = rid * 8;

    float acc[8][4];
    #pragma unroll
    for (int r = 0; r < 8; r++)
        #pragma unroll
        for (int j = 0; j < 4; j++) acc[r][j] = 0.0f;

    const float4* W4 = (const float4*)W;
    #pragma unroll 4
    for (int f = 0; f < FIN; f++) {
        float4 w = W4[f * 64 + cid];           // coalesced, L1-resident
        const float* xrow = xs + r0 * FIN + f;
        #pragma unroll
        for (int r = 0; r < 8; r++) {
            float xv = xrow[r * FIN];          // warp-broadcast LDS
            acc[r][0] = fmaf(xv, w.x, acc[r][0]);
            acc[r][1] = fmaf(xv, w.y, acc[r][1]);
            acc[r][2] = fmaf(xv, w.z, acc[r][2]);
            acc[r][3] = fmaf(xv, w.w, acc[r][3]);
        }
    }
    __syncthreads();

    // stage h into smem (reuse xs)
    {
        float4* hs4 = (float4*)xs;
        #pragma unroll
        for (int r = 0; r < 8; r++)
            hs4[(r0 + r) * 64 + cid] = make_float4(acc[r][0], acc[r][1], acc[r][2], acc[r][3]);
    }
    __syncthreads();

    // LayerNorm + logits: one warp per row
    const int wid = tid >> 5, lane = tid & 31;
    for (int rr = wid; rr < ROWS; rr += 8) {
        float v[8];
        float s = 0.0f, ss = 0.0f;
        #pragma unroll
        for (int k = 0; k < 8; k++) {
            v[k] = xs[rr * FIN + lane + 32 * k];
            s += v[k];
            ss = fmaf(v[k], v[k], ss);
        }
        #pragma unroll
        for (int o = 16; o; o >>= 1) {
            s  += __shfl_xor_sync(0xffffffffu, s,  o);
            ss += __shfl_xor_sync(0xffffffffu, ss, o);
        }
        const float mu = s * (1.0f / FOUT);
        const float var = ss * (1.0f / FOUT) - mu * mu;
        const float rstd = rsqrtf(var + 1e-5f);

        const size_t row = row_base + rr;
        float es[4] = {0, 0, 0, 0}, ed[4] = {0, 0, 0, 0};
        #pragma unroll
        for (int k = 0; k < 8; k++) {
            const int col = lane + 32 * k;
            const float n = fmaf((v[k] - mu) * rstd, gamma[col], beta[col]);
            g_h[row * FOUT + col] = n;
            const int hh = k >> 1;
            const int d = lane + 32 * (k & 1);
            es[hh] = fmaf(n, a[d], es[hh]);
            ed[hh] = fmaf(n, a[DD + d], ed[hh]);
        }
        #pragma unroll
        for (int o = 16; o; o >>= 1) {
            #pragma unroll
            for (int hh = 0; hh < 4; hh++) {
                es[hh] += __shfl_xor_sync(0xffffffffu, es[hh], o);
                ed[hh] += __shfl_xor_sync(0xffffffffu, ed[hh], o);
            }
        }
        if (lane == 0) {
            #pragma unroll
            for (int hh = 0; hh < 4; hh++) {
                g_ei[row * HH + hh] = es[hh];
                g_ej[row * HH + hh] = ed[hh];
            }
        }
    }
}

// ---------------------------------------------------------------------------
// Kernel 2: per (b,i): neighbor compaction -> leakyrelu scores -> softmax ->
// out[i,:] = sum_j alpha[j,h] * h[j,:].  Masked entries contribute exactly 0
// (exp(-1e9 - max) underflows to 0 in fp32), so skipping them is exact.
// Gather phase: 64 col-groups (float4) x 4 neighbor slices -> LDG.128,
// 1/4 the load instructions & address ALU of the scalar version.
// ---------------------------------------------------------------------------
__global__ void __launch_bounds__(256) attn_kernel(
    const float* __restrict__ adj, float* __restrict__ out)
{
    __shared__ int    nbr[NN];          // 4KB
    __shared__ float  sc[NN * HH];      // 16KB  (scores, then exp())
    __shared__ float4 red4[3 * 64];     // 3KB   (cross-slice partials)
    __shared__ int   wsum[8];
    __shared__ int   woff[8];
    __shared__ int   Ktot_s;
    __shared__ float red[8 * HH];
    __shared__ float mxs[HH];
    __shared__ float sms[HH];

    const int tid = threadIdx.x;
    const int lane = tid & 31, wid = tid >> 5;
    const size_t bi = blockIdx.x;              // b*N + i
    const size_t b  = bi >> 10;                // N = 1024

    // ---- ordered neighbor compaction (each thread owns 4 consecutive j) ----
    const float4 av = ((const float4*)(adj + bi * NN))[tid];
    const int m0 = (av.x != 0.0f), m1 = (av.y != 0.0f), m2 = (av.z != 0.0f), m3 = (av.w != 0.0f);
    int cnt = m0 + m1 + m2 + m3;
    int pre = cnt;
    #pragma unroll
    for (int o = 1; o < 32; o <<= 1) {
        int t = __shfl_up_sync(0xffffffffu, pre, o);
        if (lane >= o) pre += t;
    }
    if (lane == 31) wsum[wid] = pre;
    __syncthreads();
    if (tid == 0) {
        int acc = 0;
        #pragma unroll
        for (int w = 0; w < 8; w++) { woff[w] = acc; acc += wsum[w]; }
        Ktot_s = acc;
    }
    __syncthreads();
    {
        int p = woff[wid] + pre - cnt;
        const int j0 = tid * 4;
        if (m0) nbr[p++] = j0;
        if (m1) nbr[p++] = j0 + 1;
        if (m2) nbr[p++] = j0 + 2;
        if (m3) nbr[p++] = j0 + 3;
    }
    __syncthreads();
    const int K = Ktot_s;

    // ---- scores: leakyrelu(e_i[b,i,h] + e_j[b,j,h]) ----
    float ei[4];
    {
        const float4 e4 = ((const float4*)g_ei)[bi];
        ei[0] = e4.x; ei[1] = e4.y; ei[2] = e4.z; ei[3] = e4.w;
    }
    float lmax[4] = {-1e30f, -1e30f, -1e30f, -1e30f};
    const float4* ej4 = (const float4*)g_ej + b * NN;
    float4* sc4 = (float4*)sc;
    for (int nn = tid; nn < K; nn += 256) {
        const int j = nbr[nn];
        const float4 e4 = ej4[j];
        float s0 = ei[0] + e4.x, s1 = ei[1] + e4.y, s2 = ei[2] + e4.z, s3 = ei[3] + e4.w;
        s0 = s0 > 0.0f ? s0 : 0.2f * s0;
        s1 = s1 > 0.0f ? s1 : 0.2f * s1;
        s2 = s2 > 0.0f ? s2 : 0.2f * s2;
        s3 = s3 > 0.0f ? s3 : 0.2f * s3;
        sc4[nn] = make_float4(s0, s1, s2, s3);
        lmax[0] = fmaxf(lmax[0], s0); lmax[1] = fmaxf(lmax[1], s1);
        lmax[2] = fmaxf(lmax[2], s2); lmax[3] = fmaxf(lmax[3], s3);
    }
    // block max per head
    #pragma unroll
    for (int o = 16; o; o >>= 1)
        #pragma unroll
        for (int h = 0; h < 4; h++)
            lmax[h] = fmaxf(lmax[h], __shfl_xor_sync(0xffffffffu, lmax[h], o));
    if (lane == 0)
        #pragma unroll
        for (int h = 0; h < 4; h++) red[wid * 4 + h] = lmax[h];
    __syncthreads();
    if (tid < 4) {
        float m = -1e30f;
        #pragma unroll
        for (int w = 0; w < 8; w++) m = fmaxf(m, red[w * 4 + tid]);
        mxs[tid] = m;
    }
    __syncthreads();
    const float mx0 = mxs[0], mx1 = mxs[1], mx2 = mxs[2], mx3 = mxs[3];

    // ---- exp + block sum per head ----
    float lsum[4] = {0, 0, 0, 0};
    for (int nn = tid; nn < K; nn += 256) {
        float4 v = sc4[nn];
        v.x = __expf(v.x - mx0);
        v.y = __expf(v.y - mx1);
        v.z = __expf(v.z - mx2);
        v.w = __expf(v.w - mx3);
        sc4[nn] = v;
        lsum[0] += v.x; lsum[1] += v.y; lsum[2] += v.z; lsum[3] += v.w;
    }
    #pragma unroll
    for (int o = 16; o; o >>= 1)
        #pragma unroll
        for (int h = 0; h < 4; h++)
            lsum[h] += __shfl_xor_sync(0xffffffffu, lsum[h], o);
    if (lane == 0)
        #pragma unroll
        for (int h = 0; h < 4; h++) red[wid * 4 + h] = lsum[h];
    __syncthreads();
    if (tid < 4) {
        float s = 0.0f;
        #pragma unroll
        for (int w = 0; w < 8; w++) s += red[w * 4 + tid];
        sms[tid] = s;
    }
    __syncthreads();

    // ---- gather-accumulate: 64 float4 col-groups x 4 neighbor slices ----
    const int cg = tid & 63;           // float4 column group (cols 4cg..4cg+3)
    const int sl = tid >> 6;           // neighbor slice 0..3
    const int hh = cg >> 4;            // head of this col group
    const float4* hb4 = (const float4*)(g_h + b * NN * FOUT);
    const float* wts = sc + hh;        // weight for head hh at [nn*4 + hh]

    float4 acc = make_float4(0.0f, 0.0f, 0.0f, 0.0f);
    for (int nn = sl; nn < K; nn += 4) {
        const int j = nbr[nn];
        const float w = wts[nn * 4];
        const float4 hv = hb4[j * 64 + cg];
        acc.x = fmaf(w, hv.x, acc.x);
        acc.y = fmaf(w, hv.y, acc.y);
        acc.z = fmaf(w, hv.z, acc.z);
        acc.w = fmaf(w, hv.w, acc.w);
    }
    if (sl != 0) red4[(sl - 1) * 64 + cg] = acc;
    __syncthreads();
    if (sl == 0) {
        const float4 p1 = red4[cg];
        const float4 p2 = red4[64 + cg];
        const float4 p3 = red4[128 + cg];
        const float inv = 1.0f / sms[hh];
        float4 o;
        o.x = ((acc.x + p1.x) + (p2.x + p3.x)) * inv;
        o.y = ((acc.y + p1.y) + (p2.y + p3.y)) * inv;
        o.z = ((acc.z + p1.z) + (p2.z + p3.z)) * inv;
        o.w = ((acc.w + p1.w) + (p2.w + p3.w)) * inv;
        ((float4*)out)[bi * 64 + cg] = o;
    }
}

extern "C" void kernel_launch(void* const* d_in, const int* in_sizes, int n_in,
                              void* d_out, int out_size)
{
    const float* x     = (const float*)d_in[0];
    const float* adj   = (const float*)d_in[1];
    const float* W     = (const float*)d_in[2];
    const float* gamma = (const float*)d_in[3];
    const float* beta  = (const float*)d_in[4];
    const float* a     = (const float*)d_in[5];
    float* out = (float*)d_out;

    gemm_ln_kernel<<<(BB * NN) / ROWS, 256>>>(x, W, gamma, beta, a);
    attn_kernel<<<BB * NN, 256>>>(adj, out);
}

// round 4
// speedup vs baseline: 1.2439x; 1.0705x over previous
#include <cuda_runtime.h>
#include <cuda_fp16.h>
#include <math.h>

#define BB 8
#define NN 1024
#define FIN 256
#define FOUT 256
#define HH 4
#define DD 64
#define ROWS 32

// scratch (no cudaMalloc allowed)
__device__ __align__(16) __half g_h16[BB * NN * FOUT];  // normalized h (fp16, gather-only)
__device__ float g_ei[BB * NN * HH];                    // a_src . h  per (b,n,h)
__device__ float g_ej[BB * NN * HH];                    // a_dst . h  per (b,n,h)

// ---------------------------------------------------------------------------
// Kernel 1: h = LN(x @ W) * gamma + beta ; e_i = h.a_src ; e_j = h.a_dst
// One block = 32 rows x 256 outputs. 256 threads, reg-blocked 8x4. (R2-proven)
// ---------------------------------------------------------------------------
__global__ void __launch_bounds__(256, 2) gemm_ln_kernel(
    const float* __restrict__ x, const float* __restrict__ W,
    const float* __restrict__ gamma, const float* __restrict__ beta,
    const float* __restrict__ a)
{
    __shared__ float xs[ROWS * FIN];   // 32KB; reused as h-staging after GEMM
    const int tid = threadIdx.x;
    const size_t row_base = (size_t)blockIdx.x * ROWS;

    {
        const float4* x4 = (const float4*)(x + row_base * FIN);
        float4* xs4 = (float4*)xs;
        #pragma unroll
        for (int idx = tid; idx < ROWS * FIN / 4; idx += 256)
            xs4[idx] = x4[idx];
    }
    __syncthreads();

    const int cid = tid & 63;
    const int rid = tid >> 6;
    const int r0 = rid * 8;

    float acc[8][4];
    #pragma unroll
    for (int r = 0; r < 8; r++)
        #pragma unroll
        for (int j = 0; j < 4; j++) acc[r][j] = 0.0f;

    const float4* W4 = (const float4*)W;
    #pragma unroll 4
    for (int f = 0; f < FIN; f++) {
        float4 w = W4[f * 64 + cid];
        const float* xrow = xs + r0 * FIN + f;
        #pragma unroll
        for (int r = 0; r < 8; r++) {
            float xv = xrow[r * FIN];
            acc[r][0] = fmaf(xv, w.x, acc[r][0]);
            acc[r][1] = fmaf(xv, w.y, acc[r][1]);
            acc[r][2] = fmaf(xv, w.z, acc[r][2]);
            acc[r][3] = fmaf(xv, w.w, acc[r][3]);
        }
    }
    __syncthreads();

    {
        float4* hs4 = (float4*)xs;
        #pragma unroll
        for (int r = 0; r < 8; r++)
            hs4[(r0 + r) * 64 + cid] = make_float4(acc[r][0], acc[r][1], acc[r][2], acc[r][3]);
    }
    __syncthreads();

    // LayerNorm + logits: one warp per row
    const int wid = tid >> 5, lane = tid & 31;
    for (int rr = wid; rr < ROWS; rr += 8) {
        float v[8];
        float s = 0.0f, ss = 0.0f;
        #pragma unroll
        for (int k = 0; k < 8; k++) {
            v[k] = xs[rr * FIN + lane + 32 * k];
            s += v[k];
            ss = fmaf(v[k], v[k], ss);
        }
        #pragma unroll
        for (int o = 16; o; o >>= 1) {
            s  += __shfl_xor_sync(0xffffffffu, s,  o);
            ss += __shfl_xor_sync(0xffffffffu, ss, o);
        }
        const float mu = s * (1.0f / FOUT);
        const float var = ss * (1.0f / FOUT) - mu * mu;
        const float rstd = rsqrtf(var + 1e-5f);

        const size_t row = row_base + rr;
        float es[4] = {0, 0, 0, 0}, ed[4] = {0, 0, 0, 0};
        #pragma unroll
        for (int k = 0; k < 8; k++) {
            const int col = lane + 32 * k;
            const float n = fmaf((v[k] - mu) * rstd, gamma[col], beta[col]);
            g_h16[row * FOUT + col] = __float2half(n);
            const int hh = k >> 1;
            const int d = lane + 32 * (k & 1);
            es[hh] = fmaf(n, a[d], es[hh]);
            ed[hh] = fmaf(n, a[DD + d], ed[hh]);
        }
        #pragma unroll
        for (int o = 16; o; o >>= 1) {
            #pragma unroll
            for (int hh = 0; hh < 4; hh++) {
                es[hh] += __shfl_xor_sync(0xffffffffu, es[hh], o);
                ed[hh] += __shfl_xor_sync(0xffffffffu, ed[hh], o);
            }
        }
        if (lane == 0) {
            #pragma unroll
            for (int hh = 0; hh < 4; hh++) {
                g_ei[row * HH + hh] = es[hh];
                g_ej[row * HH + hh] = ed[hh];
            }
        }
    }
}

// ---------------------------------------------------------------------------
// Kernel 2: per (b,i): neighbor compaction -> leakyrelu scores -> softmax ->
// gather-accumulate over fp16 h rows (512B/row, half the L1 traffic of fp32).
// 32 col-groups (uint4 = 8 halves) x 8 neighbor slices. fp32 accumulation.
// ---------------------------------------------------------------------------
__global__ void __launch_bounds__(256) attn_kernel(
    const float* __restrict__ adj, float* __restrict__ out)
{
    __shared__ int    nbr[NN];            // 4KB
    __shared__ float  sc[NN * HH];        // 16KB  (scores, then exp())
    __shared__ float  redg[7 * 32 * 8];   // 7KB   (cross-slice partials)
    __shared__ int   wsum[8];
    __shared__ int   woff[8];
    __shared__ int   Ktot_s;
    __shared__ float red[8 * HH];
    __shared__ float mxs[HH];
    __shared__ float sms[HH];

    const int tid = threadIdx.x;
    const int lane = tid & 31, wid = tid >> 5;
    const size_t bi = blockIdx.x;              // b*N + i
    const size_t b  = bi >> 10;

    // ---- ordered neighbor compaction ----
    const float4 av = ((const float4*)(adj + bi * NN))[tid];
    const int m0 = (av.x != 0.0f), m1 = (av.y != 0.0f), m2 = (av.z != 0.0f), m3 = (av.w != 0.0f);
    int cnt = m0 + m1 + m2 + m3;
    int pre = cnt;
    #pragma unroll
    for (int o = 1; o < 32; o <<= 1) {
        int t = __shfl_up_sync(0xffffffffu, pre, o);
        if (lane >= o) pre += t;
    }
    if (lane == 31) wsum[wid] = pre;
    __syncthreads();
    if (tid == 0) {
        int acc = 0;
        #pragma unroll
        for (int w = 0; w < 8; w++) { woff[w] = acc; acc += wsum[w]; }
        Ktot_s = acc;
    }
    __syncthreads();
    {
        int p = woff[wid] + pre - cnt;
        const int j0 = tid * 4;
        if (m0) nbr[p++] = j0;
        if (m1) nbr[p++] = j0 + 1;
        if (m2) nbr[p++] = j0 + 2;
        if (m3) nbr[p++] = j0 + 3;
    }
    __syncthreads();
    const int K = Ktot_s;

    // ---- scores: leakyrelu(e_i + e_j) ----
    float ei[4];
    {
        const float4 e4 = ((const float4*)g_ei)[bi];
        ei[0] = e4.x; ei[1] = e4.y; ei[2] = e4.z; ei[3] = e4.w;
    }
    float lmax[4] = {-1e30f, -1e30f, -1e30f, -1e30f};
    const float4* ej4 = (const float4*)g_ej + b * NN;
    float4* sc4 = (float4*)sc;
    for (int nn = tid; nn < K; nn += 256) {
        const int j = nbr[nn];
        const float4 e4 = ej4[j];
        float s0 = ei[0] + e4.x, s1 = ei[1] + e4.y, s2 = ei[2] + e4.z, s3 = ei[3] + e4.w;
        s0 = s0 > 0.0f ? s0 : 0.2f * s0;
        s1 = s1 > 0.0f ? s1 : 0.2f * s1;
        s2 = s2 > 0.0f ? s2 : 0.2f * s2;
        s3 = s3 > 0.0f ? s3 : 0.2f * s3;
        sc4[nn] = make_float4(s0, s1, s2, s3);
        lmax[0] = fmaxf(lmax[0], s0); lmax[1] = fmaxf(lmax[1], s1);
        lmax[2] = fmaxf(lmax[2], s2); lmax[3] = fmaxf(lmax[3], s3);
    }
    #pragma unroll
    for (int o = 16; o; o >>= 1)
        #pragma unroll
        for (int h = 0; h < 4; h++)
            lmax[h] = fmaxf(lmax[h], __shfl_xor_sync(0xffffffffu, lmax[h], o));
    if (lane == 0)
        #pragma unroll
        for (int h = 0; h < 4; h++) red[wid * 4 + h] = lmax[h];
    __syncthreads();
    if (tid < 4) {
        float m = -1e30f;
        #pragma unroll
        for (int w = 0; w < 8; w++) m = fmaxf(m, red[w * 4 + tid]);
        mxs[tid] = m;
    }
    __syncthreads();
    const float mx0 = mxs[0], mx1 = mxs[1], mx2 = mxs[2], mx3 = mxs[3];

    float lsum[4] = {0, 0, 0, 0};
    for (int nn = tid; nn < K; nn += 256) {
        float4 v = sc4[nn];
        v.x = __expf(v.x - mx0);
        v.y = __expf(v.y - mx1);
        v.z = __expf(v.z - mx2);
        v.w = __expf(v.w - mx3);
        sc4[nn] = v;
        lsum[0] += v.x; lsum[1] += v.y; lsum[2] += v.z; lsum[3] += v.w;
    }
    #pragma unroll
    for (int o = 16; o; o >>= 1)
        #pragma unroll
        for (int h = 0; h < 4; h++)
            lsum[h] += __shfl_xor_sync(0xffffffffu, lsum[h], o);
    if (lane == 0)
        #pragma unroll
        for (int h = 0; h < 4; h++) red[wid * 4 + h] = lsum[h];
    __syncthreads();
    if (tid < 4) {
        float s = 0.0f;
        #pragma unroll
        for (int w = 0; w < 8; w++) s += red[w * 4 + tid];
        sms[tid] = s;
    }
    __syncthreads();

    // ---- gather-accumulate: 32 uint4 col-groups (8 halves) x 8 slices ----
    const int cg = tid & 31;           // cols 8cg .. 8cg+7
    const int sl = tid >> 5;           // neighbor slice 0..7
    const int hh = cg >> 3;            // head of this col group
    const __half* hb = g_h16 + b * NN * FOUT;
    const float* wts = sc + hh;

    float a0 = 0, a1 = 0, a2 = 0, a3 = 0, a4 = 0, a5 = 0, a6 = 0, a7 = 0;
    for (int nn = sl; nn < K; nn += 8) {
        const int j = nbr[nn];
        const float w = wts[nn * 4];
        const uint4 hv = ((const uint4*)(hb + (size_t)j * FOUT))[cg];
        const half2* hp = (const half2*)&hv;
        const float2 f0 = __half22float2(hp[0]);
        const float2 f1 = __half22float2(hp[1]);
        const float2 f2 = __half22float2(hp[2]);
        const float2 f3 = __half22float2(hp[3]);
        a0 = fmaf(w, f0.x, a0); a1 = fmaf(w, f0.y, a1);
        a2 = fmaf(w, f1.x, a2); a3 = fmaf(w, f1.y, a3);
        a4 = fmaf(w, f2.x, a4); a5 = fmaf(w, f2.y, a5);
        a6 = fmaf(w, f3.x, a6); a7 = fmaf(w, f3.y, a7);
    }
    if (sl != 0) {
        float* rp = redg + ((sl - 1) * 32 + cg) * 8;
        ((float4*)rp)[0] = make_float4(a0, a1, a2, a3);
        ((float4*)rp)[1] = make_float4(a4, a5, a6, a7);
    }
    __syncthreads();
    if (sl == 0) {
        #pragma unroll
        for (int s = 0; s < 7; s++) {
            const float* rp = redg + (s * 32 + cg) * 8;
            const float4 p0 = ((const float4*)rp)[0];
            const float4 p1 = ((const float4*)rp)[1];
            a0 += p0.x; a1 += p0.y; a2 += p0.z; a3 += p0.w;
            a4 += p1.x; a5 += p1.y; a6 += p1.z; a7 += p1.w;
        }
        const float inv = 1.0f / sms[hh];
        float4* op = (float4*)(out + bi * FOUT + cg * 8);
        op[0] = make_float4(a0 * inv, a1 * inv, a2 * inv, a3 * inv);
        op[1] = make_float4(a4 * inv, a5 * inv, a6 * inv, a7 * inv);
    }
}

extern "C" void kernel_launch(void* const* d_in, const int* in_sizes, int n_in,
                              void* d_out, int out_size)
{
    const float* x     = (const float*)d_in[0];
    const float* adj   = (const float*)d_in[1];
    const float* W     = (const float*)d_in[2];
    const float* gamma = (const float*)d_in[3];
    const float* beta  = (const float*)d_in[4];
    const float* a     = (const float*)d_in[5];
    float* out = (float*)d_out;

    gemm_ln_kernel<<<(BB * NN) / ROWS, 256>>>(x, W, gamma, beta, a);
    attn_kernel<<<BB * NN, 256>>>(adj, out);
}